// round 15
// baseline (speedup 1.0000x reference)
#include <cuda_runtime.h>

// cosine_regularizer: out = (sum(W) - N)/N^2, W = p p^T, p = row-normalized points.
// Identity: sum(W) = || sum_i p_i ||^2.
// R15: fused (a 2nd graph node costs ~5us regardless — R14 killed the throttle theory).
//      Attack the in-kernel tail = CTA completion SPREAD (cross-CTA L1tex queue,
//      spr = f(oe*MLP_p1)): split warp loads into two batches (MLP_p1 8 -> 4, below
//      the Q_th=16 knee at oe=3.46). g_rep transposed so finalize folds via LDG.128.

constexpr int N_ROWS = 16384;
constexpr int D      = 256;
constexpr int TPB    = 256;                 // 8 warps
constexpr int WARPS  = TPB / 32;
constexpr int NBLK   = 512;                 // 512*8 warps * 4 rows = 16384 rows
constexpr int NREP   = 16;                  // column-sum replicas (R6 win)

__device__ float        g_rep[D][NREP];   // transposed; reset by last block each run
__device__ unsigned int g_count;          // zero at load; reset by last block each run

__global__ void __launch_bounds__(TPB, 3)
k_fused(const float* __restrict__ pts, float* __restrict__ out) {
    const int warp = threadIdx.x >> 5;
    const int lane = threadIdx.x & 31;
    const int t    = threadIdx.x;
    const int gw   = blockIdx.x * WARPS + warp;

    float4 a0 = make_float4(0.f, 0.f, 0.f, 0.f);
    float4 a1 = make_float4(0.f, 0.f, 0.f, 0.f);

    // Two batches of 2 rows each: MLP_p1 = 4 (below the spread knee), and batch 2's
    // loads overlap batch 1's compute via ptxas pipelining of the outer loop.
#pragma unroll 1
    for (int b = 0; b < 2; b++) {
        float4 v0[2], v1[2];
#pragma unroll
        for (int k = 0; k < 2; k++) {
            const int row = gw + (2 * b + k) * (NBLK * WARPS);
            const float4* p = reinterpret_cast<const float4*>(pts) + (size_t)row * (D / 4);
            v0[k] = p[lane];        // cols 4*lane   .. +3
            v1[k] = p[32 + lane];   // cols 128+4*lane .. +3
        }

        float ss[2];
#pragma unroll
        for (int k = 0; k < 2; k++) {
            ss[k] = v0[k].x * v0[k].x + v0[k].y * v0[k].y + v0[k].z * v0[k].z + v0[k].w * v0[k].w
                  + v1[k].x * v1[k].x + v1[k].y * v1[k].y + v1[k].z * v1[k].z + v1[k].w * v1[k].w;
        }
#pragma unroll
        for (int off = 16; off > 0; off >>= 1) {
#pragma unroll
            for (int k = 0; k < 2; k++)
                ss[k] += __shfl_xor_sync(0xffffffffu, ss[k], off);
        }

#pragma unroll
        for (int k = 0; k < 2; k++) {
            const float rn = rsqrtf(ss[k]);
            a0.x += rn * v0[k].x;  a0.y += rn * v0[k].y;
            a0.z += rn * v0[k].z;  a0.w += rn * v0[k].w;
            a1.x += rn * v1[k].x;  a1.y += rn * v1[k].y;
            a1.z += rn * v1[k].z;  a1.w += rn * v1[k].w;
        }
    }

    // Block-reduce 8 warps' column partials via shared.
    __shared__ float sh[WARPS][D];
    float4* shv = reinterpret_cast<float4*>(sh[warp]);
    shv[lane]      = a0;
    shv[32 + lane] = a1;
    __syncthreads();

    float s = sh[0][t];
#pragma unroll
    for (int w = 1; w < WARPS; w++) s += sh[w][t];

    // RED into this block's replica slot (32 adds/address chip-wide).
    atomicAdd(&g_rep[t][blockIdx.x & (NREP - 1)], s);

    // ---- last-block-done finalize ----
    __shared__ unsigned int s_isLast;
    __syncthreads();   // block's REDs happen-before t0's release-arrive
    if (t == 0) {
        unsigned int old;
        asm volatile("atom.acq_rel.gpu.global.add.u32 %0, [%1], 1;"
                     : "=r"(old) : "l"(&g_count) : "memory");
        s_isLast = (old == (unsigned int)(NBLK - 1)) ? 1u : 0u;
    }
    __syncthreads();
    if (!s_isLast) return;

    if (t == 0) g_count = 0u;   // reset for next graph replay

    // Fold this column's 16 replicas: 64 contiguous bytes -> 4x LDG.128.
    const float4* rp = reinterpret_cast<const float4*>(&g_rep[t][0]);
    float4 r0 = __ldcg(rp + 0);
    float4 r1 = __ldcg(rp + 1);
    float4 r2 = __ldcg(rp + 2);
    float4 r3 = __ldcg(rp + 3);

    float4* wp = reinterpret_cast<float4*>(&g_rep[t][0]);
    const float4 z = make_float4(0.f, 0.f, 0.f, 0.f);
    wp[0] = z; wp[1] = z; wp[2] = z; wp[3] = z;    // reset for next replay

    const float v = (r0.x + r0.y + r0.z + r0.w) + (r1.x + r1.y + r1.z + r1.w)
                  + (r2.x + r2.y + r2.z + r2.w) + (r3.x + r3.y + r3.z + r3.w);

    double d = (double)v * (double)v;
#pragma unroll
    for (int off = 16; off > 0; off >>= 1)
        d += __shfl_xor_sync(0xffffffffu, d, off);

    __shared__ double wsum[WARPS];
    if (lane == 0) wsum[warp] = d;
    __syncthreads();
    if (warp == 0) {
        double x = (lane < WARPS) ? wsum[lane] : 0.0;
#pragma unroll
        for (int off = 4; off > 0; off >>= 1)
            x += __shfl_xor_sync(0xffffffffu, x, off);
        if (lane == 0) {
            const double n = (double)N_ROWS;
            out[0] = (float)((x - n) / (n * n));
        }
    }
}

extern "C" void kernel_launch(void* const* d_in, const int* in_sizes, int n_in,
                              void* d_out, int out_size) {
    const float* pts = (const float*)d_in[0];
    (void)in_sizes; (void)n_in; (void)out_size;
    k_fused<<<NBLK, TPB>>>(pts, (float*)d_out);
}

// round 16
// speedup vs baseline: 1.0030x; 1.0030x over previous
#include <cuda_runtime.h>

// cosine_regularizer: out = (sum(W) - N)/N^2, W = p p^T, p = row-normalized points.
// Identity: sum(W) = || sum_i p_i ||^2.
// R16: single kernel, DEDICATED POLLER. Block 0 streams nothing: it polls g_count
//      (one thread, ld.acquire) and finalizes the instant the 511th arrival lands —
//      launch/warmup/poll idle all overlap the streaming phase. Blocks 1..511 stream,
//      RED into replicas, release-arrive, and EXIT (no spinning -> no contention,
//      unlike R11). Finalize latency overlaps the straggler tail instead of following it.

constexpr int N_ROWS = 16384;
constexpr int D      = 256;
constexpr int TPB    = 256;                 // 8 warps
constexpr int WARPS  = TPB / 32;
constexpr int NBLK   = 512;                 // 1 poller + 511 streamers
constexpr int SWARPS = (NBLK - 1) * WARPS;  // 4088 streaming warps
constexpr int NREP   = 16;                  // column-sum replicas (R6 win)

__device__ float        g_rep[D][NREP];   // transposed; reset by poller each run
__device__ unsigned int g_count;          // zero at load; reset by poller each run

__global__ void __launch_bounds__(TPB, 3)
k_fused(const float* __restrict__ pts, float* __restrict__ out) {
    const int warp = threadIdx.x >> 5;
    const int lane = threadIdx.x & 31;
    const int t    = threadIdx.x;

    if (blockIdx.x == 0) {
        // ---- poller / finalizer block ----
        if (t == 0) {
            unsigned int c;
            do {
                asm volatile("ld.acquire.gpu.global.u32 %0, [%1];"
                             : "=r"(c) : "l"(&g_count) : "memory");
            } while (c != (unsigned int)(NBLK - 1));
        }
        __syncthreads();            // acquire-observation published to the block

        // Fold this column's 16 replicas: 64 contiguous bytes -> 4x LDG.128.
        const float4* rp = reinterpret_cast<const float4*>(&g_rep[t][0]);
        float4 r0 = __ldcg(rp + 0);
        float4 r1 = __ldcg(rp + 1);
        float4 r2 = __ldcg(rp + 2);
        float4 r3 = __ldcg(rp + 3);

        float4* wp = reinterpret_cast<float4*>(&g_rep[t][0]);
        const float4 z = make_float4(0.f, 0.f, 0.f, 0.f);
        wp[0] = z; wp[1] = z; wp[2] = z; wp[3] = z;    // reset for next replay
        if (t == 0) g_count = 0u;                      // reset for next replay

        const float v = (r0.x + r0.y + r0.z + r0.w) + (r1.x + r1.y + r1.z + r1.w)
                      + (r2.x + r2.y + r2.z + r2.w) + (r3.x + r3.y + r3.z + r3.w);

        double d = (double)v * (double)v;
#pragma unroll
        for (int off = 16; off > 0; off >>= 1)
            d += __shfl_xor_sync(0xffffffffu, d, off);

        __shared__ double wsum[WARPS];
        if (lane == 0) wsum[warp] = d;
        __syncthreads();
        if (warp == 0) {
            double x = (lane < WARPS) ? wsum[lane] : 0.0;
#pragma unroll
            for (int off = 4; off > 0; off >>= 1)
                x += __shfl_xor_sync(0xffffffffu, x, off);
            if (lane == 0) {
                const double n = (double)N_ROWS;
                out[0] = (float)((x - n) / (n * n));
            }
        }
        return;
    }

    // ---- streaming blocks (1..511) ----
    const int gw   = (blockIdx.x - 1) * WARPS + warp;   // 0..4087
    const bool has5 = (gw < N_ROWS - 4 * SWARPS);       // 32 warps take a 5th row

    // Batch-issue loads: 4 rows always (8 LDG.128), plus optional 5th row.
    float4 v0[5], v1[5];
#pragma unroll
    for (int k = 0; k < 4; k++) {
        const int row = gw + k * SWARPS;
        const float4* p = reinterpret_cast<const float4*>(pts) + (size_t)row * (D / 4);
        v0[k] = p[lane];
        v1[k] = p[32 + lane];
    }
    {
        const int r5 = has5 ? (4 * SWARPS + gw) : gw;   // safe addr; zeroed later
        const float4* p = reinterpret_cast<const float4*>(pts) + (size_t)r5 * (D / 4);
        v0[4] = p[lane];
        v1[4] = p[32 + lane];
    }

    // Per-row sum of squares; 5 interleaved warp reductions.
    float ss[5];
#pragma unroll
    for (int k = 0; k < 5; k++) {
        ss[k] = v0[k].x * v0[k].x + v0[k].y * v0[k].y + v0[k].z * v0[k].z + v0[k].w * v0[k].w
              + v1[k].x * v1[k].x + v1[k].y * v1[k].y + v1[k].z * v1[k].z + v1[k].w * v1[k].w;
    }
#pragma unroll
    for (int off = 16; off > 0; off >>= 1) {
#pragma unroll
        for (int k = 0; k < 5; k++)
            ss[k] += __shfl_xor_sync(0xffffffffu, ss[k], off);
    }

    // rnorm * row into per-lane column accumulators (5th row zeroed if absent).
    float4 a0 = make_float4(0.f, 0.f, 0.f, 0.f);
    float4 a1 = make_float4(0.f, 0.f, 0.f, 0.f);
#pragma unroll
    for (int k = 0; k < 5; k++) {
        const float rn = (k < 4 || has5) ? rsqrtf(ss[k]) : 0.0f;
        a0.x += rn * v0[k].x;  a0.y += rn * v0[k].y;
        a0.z += rn * v0[k].z;  a0.w += rn * v0[k].w;
        a1.x += rn * v1[k].x;  a1.y += rn * v1[k].y;
        a1.z += rn * v1[k].z;  a1.w += rn * v1[k].w;
    }

    // Block-reduce 8 warps' column partials via shared.
    __shared__ float sh[WARPS][D];
    float4* shv = reinterpret_cast<float4*>(sh[warp]);
    shv[lane]      = a0;
    shv[32 + lane] = a1;
    __syncthreads();

    float s = sh[0][t];
#pragma unroll
    for (int w = 1; w < WARPS; w++) s += sh[w][t];

    // RED into this block's replica slot (~32 adds/address chip-wide).
    atomicAdd(&g_rep[t][blockIdx.x & (NREP - 1)], s);

    // Release-arrive: this block's REDs precede the increment. Then exit.
    __syncthreads();
    if (t == 0) {
        unsigned int old;
        asm volatile("atom.release.gpu.global.add.u32 %0, [%1], 1;"
                     : "=r"(old) : "l"(&g_count) : "memory");
    }
}

extern "C" void kernel_launch(void* const* d_in, const int* in_sizes, int n_in,
                              void* d_out, int out_size) {
    const float* pts = (const float*)d_in[0];
    (void)in_sizes; (void)n_in; (void)out_size;
    k_fused<<<NBLK, TPB>>>(pts, (float*)d_out);
}